// round 7
// baseline (speedup 1.0000x reference)
#include <cuda_runtime.h>

typedef unsigned long long ull;

#define Bb 256
#define Tt 512
#define Vv 30000
#define Ee 256

// ---------------- static device scratch ----------------
__device__ float g_embedW[(size_t)Vv * 192];            // [V][192] fwd 0..95, bwd 96..191 (bih folded, r/z pre-halved)
__device__ float g_x1[(size_t)Bb * Tt * 64];            // layer0 outputs [B][T][64]
__device__ float g_gi1[((size_t)Bb * Tt + 6) * 192];    // layer1 input gates, 3 guard rows each end
__device__ float g_top[Bb * 64];
__device__ int   g_len[Bb];

#define GI1_GUARD (3 * 192)

// ---------------- fast math ----------------
__device__ __forceinline__ float fast_tanh(float x) {
    float y; asm("tanh.approx.f32 %0, %1;" : "=f"(y) : "f"(x));
    return y;
}
__device__ __forceinline__ void fma2(ull& d, ull a, ull b) {
    asm("fma.rn.f32x2 %0, %1, %2, %0;" : "+l"(d) : "l"(a), "l"(b));
}
__device__ __forceinline__ ull add2(ull a, ull b) {
    ull r; asm("add.rn.f32x2 %0, %1, %2;" : "=l"(r) : "l"(a), "l"(b));
    return r;
}
__device__ __forceinline__ ull dup2(float v) {
    ull r; asm("mov.b64 %0, {%1, %1};" : "=l"(r) : "f"(v));
    return r;
}
__device__ __forceinline__ ull pack2(float lo, float hi) {
    ull r; asm("mov.b64 %0, {%1, %2};" : "=l"(r) : "f"(lo), "f"(hi));
    return r;
}
__device__ __forceinline__ float hsum2(ull v) {
    unsigned lo, hi;
    asm("mov.b64 {%0, %1}, %2;" : "=r"(lo), "=r"(hi) : "l"(v));
    return __uint_as_float(lo) + __uint_as_float(hi);
}

// ---------------- lengths from attention mask (prefix mask) ----------------
__global__ void lens_kernel(const int* __restrict__ mask)
{
    int w = (blockIdx.x * blockDim.x + threadIdx.x) >> 5;
    int lane = threadIdx.x & 31;
    if (w >= Bb) return;
    int s = 0;
    for (int i = lane; i < Tt; i += 32) s += mask[w * Tt + i];
#pragma unroll
    for (int off = 16; off; off >>= 1) s += __shfl_xor_sync(0xffffffffu, s, off);
    if (lane == 0) g_len[w] = s;
}

// ---------------- fused GEMM: C[M,192] = (A[M,K] @ [Wf;Wb]^T + bias) * colscale ----------------
// BM=64, BN=192, BK=32, 256 threads, single-buffer smem, 3 CTAs/SM.
__global__ __launch_bounds__(256, 3)
void gemm192_kernel(const float* __restrict__ A,
                    const float* __restrict__ Wf, const float* __restrict__ Wb,
                    const float* __restrict__ bf, const float* __restrict__ bb_,
                    float* __restrict__ C, int M, int K,
                    const int* __restrict__ rowmask)
{
    __shared__ float As[32][68];
    __shared__ float Bs[32][196];

    int m0 = blockIdx.x * 64;
    if (rowmask && rowmask[m0] == 0) return;   // prefix mask: whole 64-row block padded

    int tid = threadIdx.x;
    int tx = tid & 31;        // cols tx + 32*j, j=0..5
    int ty = tid >> 5;        // rows ty*8 .. ty*8+7
    int lkk = tid & 31;       // k within tile
    int lrow = tid >> 5;      // 0..7, rows stride 8

    const float* abase = A + (m0 + lrow) * K + lkk;
    const float* wfb = Wf + lrow * K + lkk;
    const float* wbb = Wb + lrow * K + lkk;
    bool arow_ok[8];
#pragma unroll
    for (int p = 0; p < 8; p++) arow_ok[p] = (m0 + lrow + 8 * p) < M;
    int K8 = K * 8;

    ull acc[4][6];
#pragma unroll
    for (int i = 0; i < 4; i++)
#pragma unroll
        for (int j = 0; j < 6; j++) acc[i][j] = 0ull;

    for (int k0 = 0; k0 < K; k0 += 32) {
#pragma unroll
        for (int p = 0; p < 8; p++)
            As[lkk][lrow + 8 * p] = arow_ok[p] ? abase[p * K8 + k0] : 0.f;
#pragma unroll
        for (int p = 0; p < 12; p++)
            Bs[lkk][lrow + 8 * p] = wfb[p * K8 + k0];
#pragma unroll
        for (int p = 12; p < 24; p++)
            Bs[lkk][lrow + 8 * p] = wbb[(p - 12) * K8 + k0];
        __syncthreads();
#pragma unroll
        for (int k = 0; k < 32; k++) {
            ulonglong2 q0 = *(const ulonglong2*)&As[k][ty * 8];
            ulonglong2 q1 = *(const ulonglong2*)&As[k][ty * 8 + 4];
            ull a2[4] = { q0.x, q0.y, q1.x, q1.y };
            ull b2[6];
#pragma unroll
            for (int j = 0; j < 6; j++) b2[j] = dup2(Bs[k][tx + 32 * j]);
#pragma unroll
            for (int i = 0; i < 4; i++)
#pragma unroll
                for (int j = 0; j < 6; j++)
                    fma2(acc[i][j], a2[i], b2[j]);
        }
        __syncthreads();
    }

#pragma unroll
    for (int j = 0; j < 6; j++) {
        int n = tx + 32 * j;
        // j: 0=r_f 1=z_f 2=n_f 3=r_b 4=z_b 5=n_b ; r/z pre-halved for tanh-form sigmoid
        float scale = (j == 2 || j == 5) ? 1.0f : 0.5f;
        float bias = (j < 3) ? bf[n] : bb_[n - 96];
#pragma unroll
        for (int i = 0; i < 4; i++) {
            int gm0 = m0 + ty * 8 + 2 * i;
            unsigned lo, hi;
            asm("mov.b64 {%0, %1}, %2;" : "=r"(lo), "=r"(hi) : "l"(acc[i][j]));
            if (gm0 < M)     C[(size_t)gm0 * 192 + n]       = (__uint_as_float(lo) + bias) * scale;
            if (gm0 + 1 < M) C[(size_t)(gm0 + 1) * 192 + n] = (__uint_as_float(hi) + bias) * scale;
        }
    }
}

// ---------------- GRU recurrence: warp = (batch, dir) ----------------
// Guard rows (gi buffer / sid table) make the distance-3 prefetch branch- and clamp-free.
template<bool L0>
__global__ __launch_bounds__(128)
void gru_kernel(const float* __restrict__ gi,   // L1: guard-offset base
                const int* __restrict__ ids,
                const float* __restrict__ Whh_f, const float* __restrict__ bhh_f,
                const float* __restrict__ Whh_b, const float* __restrict__ bhh_b)
{
    __shared__ float sh[4][2][32];        // [warp][parity][lane]
    __shared__ int   sid[4][Tt + 6];      // L0 only: +3 guard each end

    int wib = threadIdx.x >> 5;
    int lane = threadIdx.x & 31;
    int w = blockIdx.x * 4 + wib;
    int dir = w & 1;
    int b   = w >> 1;
    const float* Whh = dir ? Whh_b : Whh_f;
    const float* bhh = dir ? bhh_b : bhh_f;

    // Whh rows packed as f32x2 pairs; r/z rows pre-halved (tanh-form sigmoid)
    ull Wr2[16], Wz2[16], Wn2[16];
#pragma unroll
    for (int q = 0; q < 8; q++) {
        float4 v;
        v = *(const float4*)&Whh[lane * 32 + q * 4];
        Wr2[2*q]   = pack2(0.5f * v.x, 0.5f * v.y);
        Wr2[2*q+1] = pack2(0.5f * v.z, 0.5f * v.w);
        v = *(const float4*)&Whh[(32 + lane) * 32 + q * 4];
        Wz2[2*q]   = pack2(0.5f * v.x, 0.5f * v.y);
        Wz2[2*q+1] = pack2(0.5f * v.z, 0.5f * v.w);
        v = *(const float4*)&Whh[(64 + lane) * 32 + q * 4];
        Wn2[2*q]   = pack2(v.x, v.y);
        Wn2[2*q+1] = pack2(v.z, v.w);
    }
    ull bR = pack2(0.5f * bhh[lane], 0.f);
    ull bZ = pack2(0.5f * bhh[32 + lane], 0.f);
    ull bN = pack2(bhh[64 + lane], 0.f);

    int len = g_len[b];

    if (L0) {
        const int* idrow = ids + b * Tt;
        for (int i = lane; i < len; i += 32) sid[wib][i + 3] = idrow[i];
        if (lane < 3) {                      // zero-token guards both ends
            sid[wib][lane] = 0;
            sid[wib][len + 3 + lane] = 0;
        }
        __syncwarp();
    }

    int tstep = dir ? -1 : 1;
    int tcur  = dir ? (len - 1) : 0;

    // direction-adjusted base pointers
    const float* gi0  = gi + dir * 96;                              // L0: + sid[t+3]*192
    const float* gib  = gi + (size_t)b * Tt * 192 + dir * 96;       // L1: + t*192 (guard-safe)

    auto gip = [&](int t) -> const float* {
        if (L0) return gi0 + (size_t)sid[wib][t + 3] * 192;
        else    return gib + (long)t * 192;
    };

    // distance-3 prefetch pipeline (guards -> no clamp, no branches)
    const float* p;
    p = gip(tcur);
    float p0r = __ldg(p + lane), p0z = __ldg(p + 32 + lane), p0n = __ldg(p + 64 + lane);
    p = gip(tcur + tstep);
    float p1r = __ldg(p + lane), p1z = __ldg(p + 32 + lane), p1n = __ldg(p + 64 + lane);
    p = gip(tcur + 2 * tstep);
    float p2r = __ldg(p + lane), p2z = __ldg(p + 32 + lane), p2n = __ldg(p + 64 + lane);

    float h = 0.f;
    float* outp = L0 ? (g_x1 + ((size_t)b * Tt + tcur) * 64 + dir * 32 + lane) : nullptr;
    int outstep = tstep * 64;

#pragma unroll 2
    for (int s = 0; s < len; s++) {
        float cr = p0r, cz = p0z, cn = p0n;
        p0r = p1r; p0z = p1z; p0n = p1n;
        p1r = p2r; p1z = p2z; p1n = p2n;
        p = gip(tcur + 3 * tstep);
        p2r = __ldg(p + lane); p2z = __ldg(p + 32 + lane); p2n = __ldg(p + 64 + lane);

        int par = s & 1;
        sh[wib][par][lane] = h;
        __syncwarp();
        ull h2[16];
#pragma unroll
        for (int i = 0; i < 8; i++) {
            ulonglong2 q2 = *(const ulonglong2*)&sh[wib][par][4 * i];
            h2[2 * i] = q2.x; h2[2 * i + 1] = q2.y;
        }

        ull ra = bR, rb = 0ull, za = bZ, zb = 0ull, na = bN, nb2 = 0ull;
#pragma unroll
        for (int k = 0; k < 16; k += 2) {
            fma2(na,  Wn2[k],     h2[k]);
            fma2(nb2, Wn2[k + 1], h2[k + 1]);
            fma2(ra,  Wr2[k],     h2[k]);
            fma2(rb,  Wr2[k + 1], h2[k + 1]);
            fma2(za,  Wz2[k],     h2[k]);
            fma2(zb,  Wz2[k + 1], h2[k + 1]);
        }
        float ar = hsum2(add2(ra, rb));
        float az = hsum2(add2(za, zb));
        float an = hsum2(add2(na, nb2));

        // sigmoid(x) = 0.5 + 0.5*tanh(x/2); r/z args pre-halved upstream
        float r = fmaf(0.5f, fast_tanh(cr + ar), 0.5f);
        float z = fmaf(0.5f, fast_tanh(cz + az), 0.5f);
        float n = fast_tanh(fmaf(r, an, cn));
        h = fmaf(z, h - n, n);

        if (L0) { *outp = h; outp += outstep; }
        tcur += tstep;
    }
    if (!L0)
        g_top[b * 64 + dir * 32 + lane] = h;
}

// ---------------- final linear [B,64] @ [6,64]^T + bias ----------------
__global__ void out_kernel(const float* __restrict__ Wout, const float* __restrict__ bout,
                           float* __restrict__ out)
{
    int w = (blockIdx.x * blockDim.x + threadIdx.x) >> 5;
    int lane = threadIdx.x & 31;
    if (w >= Bb) return;
    float t0 = g_top[w * 64 + lane];
    float t1 = g_top[w * 64 + 32 + lane];
#pragma unroll
    for (int o = 0; o < 6; o++) {
        float s = t0 * Wout[o * 64 + lane] + t1 * Wout[o * 64 + 32 + lane];
#pragma unroll
        for (int off = 16; off; off >>= 1) s += __shfl_xor_sync(0xffffffffu, s, off);
        if (lane == 0) out[w * 6 + o] = s + bout[o];
    }
}

// ---------------- launch ----------------
extern "C" void kernel_launch(void* const* d_in, const int* in_sizes, int n_in,
                              void* d_out, int out_size)
{
    const int*   ids     = (const int*)d_in[0];
    const int*   mask    = (const int*)d_in[1];
    const float* embed   = (const float*)d_in[2];
    const float* Wih_l0f = (const float*)d_in[3];
    const float* Whh_l0f = (const float*)d_in[4];
    const float* bih_l0f = (const float*)d_in[5];
    const float* bhh_l0f = (const float*)d_in[6];
    const float* Wih_l0b = (const float*)d_in[7];
    const float* Whh_l0b = (const float*)d_in[8];
    const float* bih_l0b = (const float*)d_in[9];
    const float* bhh_l0b = (const float*)d_in[10];
    const float* Wih_l1f = (const float*)d_in[11];
    const float* Whh_l1f = (const float*)d_in[12];
    const float* bih_l1f = (const float*)d_in[13];
    const float* bhh_l1f = (const float*)d_in[14];
    const float* Wih_l1b = (const float*)d_in[15];
    const float* Whh_l1b = (const float*)d_in[16];
    const float* bih_l1b = (const float*)d_in[17];
    const float* bhh_l1b = (const float*)d_in[18];
    const float* Wout    = (const float*)d_in[19];
    const float* bout    = (const float*)d_in[20];
    float* out = (float*)d_out;

    float *p_embedW = nullptr, *p_x1 = nullptr, *p_gi1_raw = nullptr;
    cudaGetSymbolAddress((void**)&p_embedW, g_embedW);
    cudaGetSymbolAddress((void**)&p_x1, g_x1);
    cudaGetSymbolAddress((void**)&p_gi1_raw, g_gi1);
    float* p_gi1 = p_gi1_raw + GI1_GUARD;   // guard-offset base

    // 1) lengths
    lens_kernel<<<8, 1024>>>(mask);
    // 2) embedW = (embed @ [Wih_l0f;Wih_l0b]^T + bias) * colscale
    gemm192_kernel<<<(Vv + 63) / 64, 256>>>(embed, Wih_l0f, Wih_l0b, bih_l0f, bih_l0b,
                                            p_embedW, Vv, Ee, nullptr);
    // 3) layer-0 bidirectional recurrence -> x1
    gru_kernel<true><<<128, 128>>>(p_embedW, ids, Whh_l0f, bhh_l0f, Whh_l0b, bhh_l0b);
    // 4) gi1 = (x1 @ [Wih_l1f;Wih_l1b]^T + bias) * colscale  (masked blocks skipped)
    gemm192_kernel<<<(Bb * Tt) / 64, 256>>>(p_x1, Wih_l1f, Wih_l1b, bih_l1f, bih_l1b,
                                            p_gi1, Bb * Tt, 64, mask);
    // 5) layer-1 recurrence -> final hiddens
    gru_kernel<false><<<128, 128>>>(p_gi1, nullptr, Whh_l1f, bhh_l1f, Whh_l1b, bhh_l1b);
    // 6) output projection
    out_kernel<<<8, 1024>>>(Wout, bout, out);
}